// round 1
// baseline (speedup 1.0000x reference)
#include <cuda_runtime.h>

#define NN 100000
#define EE 640000
#define HH 128
#define BN_EPS 1e-5f

// ---------------- device scratch ----------------
__device__ float g_agg[(size_t)NN * HH];
__device__ float g_y[(size_t)NN * HH];
__device__ float g_x[(size_t)NN * HH];
__device__ float g_wt[3][2 * HH * HH];   // [layer][k' (0..255)][h] transposed concat [Wl^T ; Wr^T]
__device__ float g_wt3[HH * HH];         // W1^T
__device__ int   g_deg[NN];
__device__ int   g_off[NN + 1];
__device__ int   g_cur[NN];
__device__ int   g_ssrc[EE];
__device__ float g_colsum[HH];
__device__ float g_colsq[HH];
__device__ float g_mu[HH];
__device__ float g_inv[HH];

// ---------------- weight transpose (128x128) ----------------
// dsel: 0=Wl0 1=Wr0 2=Wl1 3=Wr1 4=Wl2 5=Wr2 6=W1
__global__ void k_transpose(const float* __restrict__ src, int dsel) {
    float* dst = (dsel < 6) ? (g_wt[dsel >> 1] + (dsel & 1) * HH * HH) : g_wt3;
    __shared__ float t[32][33];
    int bx = blockIdx.x, by = blockIdx.y;
    int x = bx * 32 + threadIdx.x;
    for (int j = threadIdx.y; j < 32; j += 8)
        t[j][threadIdx.x] = src[(by * 32 + j) * HH + x];
    __syncthreads();
    int xo = by * 32 + threadIdx.x;
    for (int j = threadIdx.y; j < 32; j += 8)
        dst[(bx * 32 + j) * HH + xo] = t[threadIdx.x][j];
}

// ---------------- CSR build ----------------
__global__ void k_zero() {
    int i = blockIdx.x * blockDim.x + threadIdx.x;
    if (i < NN) { g_deg[i] = 0; g_cur[i] = 0; }
}

__global__ void k_count(const int* __restrict__ dst) {
    int e = blockIdx.x * blockDim.x + threadIdx.x;
    if (e < EE) atomicAdd(&g_deg[dst[e]], 1);
}

__global__ void k_scan() {
    __shared__ int sh[1024];
    __shared__ int carry;
    int tid = threadIdx.x;
    if (tid == 0) { carry = 0; g_off[0] = 0; }
    __syncthreads();
    for (int base = 0; base < NN; base += 4096) {
        int i0 = base + tid * 4;
        int a = (i0     < NN) ? g_deg[i0]     : 0;
        int b = (i0 + 1 < NN) ? g_deg[i0 + 1] : 0;
        int c = (i0 + 2 < NN) ? g_deg[i0 + 2] : 0;
        int d = (i0 + 3 < NN) ? g_deg[i0 + 3] : 0;
        int s = a + b + c + d;
        sh[tid] = s;
        __syncthreads();
        for (int o = 1; o < 1024; o <<= 1) {
            int t = (tid >= o) ? sh[tid - o] : 0;
            __syncthreads();
            sh[tid] += t;
            __syncthreads();
        }
        int excl = sh[tid] - s;
        int run = carry + excl;
        if (i0     < NN) g_off[i0 + 1] = run + a;
        if (i0 + 1 < NN) g_off[i0 + 2] = run + a + b;
        if (i0 + 2 < NN) g_off[i0 + 3] = run + a + b + c;
        if (i0 + 3 < NN) g_off[i0 + 4] = run + s;
        int tot = sh[1023];
        __syncthreads();
        if (tid == 0) carry += tot;
        __syncthreads();
    }
}

__global__ void k_bucket(const int* __restrict__ src, const int* __restrict__ dst) {
    int e = blockIdx.x * blockDim.x + threadIdx.x;
    if (e < EE) {
        int d = dst[e];
        int p = atomicAdd(&g_cur[d], 1);
        g_ssrc[g_off[d] + p] = src[e];
    }
}

// ---------------- mean aggregation: one warp per node ----------------
__global__ void k_agg(const float* __restrict__ xext) {
    const float* X = xext ? xext : g_x;
    int w = (blockIdx.x * blockDim.x + threadIdx.x) >> 5;
    int lane = threadIdx.x & 31;
    if (w >= NN) return;
    int s = g_off[w], e = g_off[w + 1];
    float4 acc = make_float4(0.f, 0.f, 0.f, 0.f);
    float4 acc2 = make_float4(0.f, 0.f, 0.f, 0.f);
    int j = s;
    for (; j + 1 < e; j += 2) {
        int s0 = g_ssrc[j];
        int s1 = g_ssrc[j + 1];
        float4 v0 = *(const float4*)(X + (size_t)s0 * HH + lane * 4);
        float4 v1 = *(const float4*)(X + (size_t)s1 * HH + lane * 4);
        acc.x += v0.x; acc.y += v0.y; acc.z += v0.z; acc.w += v0.w;
        acc2.x += v1.x; acc2.y += v1.y; acc2.z += v1.z; acc2.w += v1.w;
    }
    if (j < e) {
        int s0 = g_ssrc[j];
        float4 v0 = *(const float4*)(X + (size_t)s0 * HH + lane * 4);
        acc.x += v0.x; acc.y += v0.y; acc.z += v0.z; acc.w += v0.w;
    }
    acc.x += acc2.x; acc.y += acc2.y; acc.z += acc2.z; acc.w += acc2.w;
    int d = e - s;
    float invd = (d > 0) ? (1.0f / (float)d) : 0.0f;
    acc.x *= invd; acc.y *= invd; acc.z *= invd; acc.w *= invd;
    *(float4*)(g_agg + (size_t)w * HH + lane * 4) = acc;
}

// ---------------- fused dual-input SGEMM: y = [agg|x] @ WT + bias ----------------
// block tile: 128 rows x 128 cols, 256 threads, thread tile 8x8
__global__ void __launch_bounds__(256) k_gemm(const float* __restrict__ A1ext,
                                              const float* __restrict__ bias,
                                              int wsel, int Ktot) {
    const float* A1 = A1ext ? A1ext : g_x;
    const float* WT = (wsel < 3) ? g_wt[wsel] : g_wt3;
    extern __shared__ float sm[];
    float* Bs = sm;                 // [Ktot][128]
    float* As = sm + Ktot * HH;     // 2 x [8][128]

    int tid = threadIdx.x;
    int tx = tid & 15, ty = tid >> 4;
    int m0 = blockIdx.x * 128;

    for (int idx = tid * 4; idx < Ktot * HH; idx += 1024)
        *(float4*)(Bs + idx) = *(const float4*)(WT + idx);

    int lrow = tid & 127;
    int kq = (tid >> 7) * 4;          // 0 or 4
    int grow = m0 + lrow;
    bool rok = grow < NN;

    float acc[8][8];
#pragma unroll
    for (int i = 0; i < 8; i++)
#pragma unroll
        for (int jj = 0; jj < 8; jj++) acc[i][jj] = 0.f;

    int nk = Ktot / 8;

    // chunk 0 load (gk always < 128)
    {
        const float* S = (Ktot == 256) ? g_agg : A1;
        float4 av = rok ? *(const float4*)(S + (size_t)grow * HH + kq)
                        : make_float4(0.f, 0.f, 0.f, 0.f);
        float* D = As;
        D[(kq + 0) * HH + lrow] = av.x;
        D[(kq + 1) * HH + lrow] = av.y;
        D[(kq + 2) * HH + lrow] = av.z;
        D[(kq + 3) * HH + lrow] = av.w;
    }
    __syncthreads();

    for (int kc = 0; kc < nk; kc++) {
        float4 nxt = make_float4(0.f, 0.f, 0.f, 0.f);
        if (kc + 1 < nk) {
            int gk = (kc + 1) * 8 + kq;
            const float* S;
            int kk = gk;
            if (Ktot == 256) {
                if (gk >= 128) { S = A1; kk = gk - 128; }
                else           { S = g_agg; }
            } else {
                S = A1;
            }
            if (rok) nxt = *(const float4*)(S + (size_t)grow * HH + kk);
        }
        const float* cur = As + (kc & 1) * 8 * HH;
#pragma unroll
        for (int kk = 0; kk < 8; kk++) {
            float4 a0 = *(const float4*)(cur + kk * HH + ty * 4);
            float4 a1 = *(const float4*)(cur + kk * HH + ty * 4 + 64);
            const float* br = Bs + (kc * 8 + kk) * HH;
            float4 b0 = *(const float4*)(br + tx * 4);
            float4 b1 = *(const float4*)(br + tx * 4 + 64);
            float a[8] = {a0.x, a0.y, a0.z, a0.w, a1.x, a1.y, a1.z, a1.w};
            float b[8] = {b0.x, b0.y, b0.z, b0.w, b1.x, b1.y, b1.z, b1.w};
#pragma unroll
            for (int i = 0; i < 8; i++)
#pragma unroll
                for (int jj = 0; jj < 8; jj++)
                    acc[i][jj] = fmaf(a[i], b[jj], acc[i][jj]);
        }
        if (kc + 1 < nk) {
            float* D = As + ((kc + 1) & 1) * 8 * HH;
            D[(kq + 0) * HH + lrow] = nxt.x;
            D[(kq + 1) * HH + lrow] = nxt.y;
            D[(kq + 2) * HH + lrow] = nxt.z;
            D[(kq + 3) * HH + lrow] = nxt.w;
        }
        __syncthreads();
    }

    float4 bi0 = *(const float4*)(bias + tx * 4);
    float4 bi1 = *(const float4*)(bias + tx * 4 + 64);
#pragma unroll
    for (int i = 0; i < 8; i++) {
        int row = m0 + ty * 4 + ((i < 4) ? i : (60 + i));
        if (row < NN) {
            float4 o0 = make_float4(acc[i][0] + bi0.x, acc[i][1] + bi0.y,
                                    acc[i][2] + bi0.z, acc[i][3] + bi0.w);
            float4 o1 = make_float4(acc[i][4] + bi1.x, acc[i][5] + bi1.y,
                                    acc[i][6] + bi1.z, acc[i][7] + bi1.w);
            *(float4*)(g_y + (size_t)row * HH + tx * 4) = o0;
            *(float4*)(g_y + (size_t)row * HH + tx * 4 + 64) = o1;
        }
    }
}

// ---------------- batch-norm statistics ----------------
__global__ void k_zstats() {
    int i = threadIdx.x;
    g_colsum[i] = 0.f;
    g_colsq[i] = 0.f;
}

__global__ void k_stats() {
    int tid = threadIdx.x;
    int tx = tid & 31, ty = tid >> 5;
    float4 s = make_float4(0.f, 0.f, 0.f, 0.f);
    float4 q = make_float4(0.f, 0.f, 0.f, 0.f);
    for (int r = blockIdx.x * 8 + ty; r < NN; r += gridDim.x * 8) {
        float4 v = *(const float4*)(g_y + (size_t)r * HH + tx * 4);
        s.x += v.x; s.y += v.y; s.z += v.z; s.w += v.w;
        q.x += v.x * v.x; q.y += v.y * v.y; q.z += v.z * v.z; q.w += v.w * v.w;
    }
    __shared__ float ss[8][HH];
    __shared__ float sq[8][HH];
    *(float4*)&ss[ty][tx * 4] = s;
    *(float4*)&sq[ty][tx * 4] = q;
    __syncthreads();
    if (ty == 0) {
#pragma unroll
        for (int r = 1; r < 8; r++) {
            float4 vs = *(const float4*)&ss[r][tx * 4];
            float4 vq = *(const float4*)&sq[r][tx * 4];
            s.x += vs.x; s.y += vs.y; s.z += vs.z; s.w += vs.w;
            q.x += vq.x; q.y += vq.y; q.z += vq.z; q.w += vq.w;
        }
        atomicAdd(&g_colsum[tx * 4 + 0], s.x);
        atomicAdd(&g_colsum[tx * 4 + 1], s.y);
        atomicAdd(&g_colsum[tx * 4 + 2], s.z);
        atomicAdd(&g_colsum[tx * 4 + 3], s.w);
        atomicAdd(&g_colsq[tx * 4 + 0], q.x);
        atomicAdd(&g_colsq[tx * 4 + 1], q.y);
        atomicAdd(&g_colsq[tx * 4 + 2], q.z);
        atomicAdd(&g_colsq[tx * 4 + 3], q.w);
    }
}

__global__ void k_finstats() {
    int c = threadIdx.x;
    float mu = g_colsum[c] / (float)NN;
    float var = g_colsq[c] / (float)NN - mu * mu;
    g_mu[c] = mu;
    g_inv[c] = rsqrtf(var + BN_EPS);
}

__global__ void k_bnrelu() {
    size_t i = ((size_t)blockIdx.x * 256 + threadIdx.x) * 4;
    if (i >= (size_t)NN * HH) return;
    int c = (int)(i & (HH - 1));
    float4 v = *(const float4*)(g_y + i);
    float4 m = *(const float4*)(g_mu + c);
    float4 iv = *(const float4*)(g_inv + c);
    v.x = fmaxf(0.f, (v.x - m.x) * iv.x);
    v.y = fmaxf(0.f, (v.y - m.y) * iv.y);
    v.z = fmaxf(0.f, (v.z - m.z) * iv.z);
    v.w = fmaxf(0.f, (v.w - m.w) * iv.w);
    *(float4*)(g_x + i) = v;
}

// ---------------- final projection to 2 outputs ----------------
__global__ void k_final(const float* __restrict__ W2, const float* __restrict__ b2,
                        float* __restrict__ out) {
    int w = (blockIdx.x * blockDim.x + threadIdx.x) >> 5;
    int lane = threadIdx.x & 31;
    if (w >= NN) return;
    float4 xv = *(const float4*)(g_x + (size_t)w * HH + lane * 4);
    float4 w0 = *(const float4*)(W2 + lane * 4);
    float4 w1 = *(const float4*)(W2 + HH + lane * 4);
    float d0 = xv.x * w0.x + xv.y * w0.y + xv.z * w0.z + xv.w * w0.w;
    float d1 = xv.x * w1.x + xv.y * w1.y + xv.z * w1.z + xv.w * w1.w;
#pragma unroll
    for (int o = 16; o; o >>= 1) {
        d0 += __shfl_xor_sync(0xFFFFFFFFu, d0, o);
        d1 += __shfl_xor_sync(0xFFFFFFFFu, d1, o);
    }
    if (lane == 0) {
        out[(size_t)w * 2 + 0] = d0 + b2[0];
        out[(size_t)w * 2 + 1] = d1 + b2[1];
    }
}

// ---------------- host launch ----------------
extern "C" void kernel_launch(void* const* d_in, const int* in_sizes, int n_in,
                              void* d_out, int out_size) {
    const float* x   = (const float*)d_in[0];
    const int*   ei  = (const int*)d_in[1];
    const int*   src = ei;
    const int*   dst = ei + EE;
    const float* Wl0 = (const float*)d_in[2];
    const float* bl0 = (const float*)d_in[3];
    const float* Wr0 = (const float*)d_in[4];
    const float* Wl1 = (const float*)d_in[5];
    const float* bl1 = (const float*)d_in[6];
    const float* Wr1 = (const float*)d_in[7];
    const float* Wl2 = (const float*)d_in[8];
    const float* bl2 = (const float*)d_in[9];
    const float* Wr2 = (const float*)d_in[10];
    const float* W1  = (const float*)d_in[11];
    const float* b1  = (const float*)d_in[12];
    const float* W2  = (const float*)d_in[13];
    const float* b2  = (const float*)d_in[14];

    cudaFuncSetAttribute(k_gemm, cudaFuncAttributeMaxDynamicSharedMemorySize, 139264);

    dim3 tb(32, 8);
    dim3 tg(4, 4);
    k_transpose<<<tg, tb>>>(Wl0, 0);
    k_transpose<<<tg, tb>>>(Wr0, 1);
    k_transpose<<<tg, tb>>>(Wl1, 2);
    k_transpose<<<tg, tb>>>(Wr1, 3);
    k_transpose<<<tg, tb>>>(Wl2, 4);
    k_transpose<<<tg, tb>>>(Wr2, 5);
    k_transpose<<<tg, tb>>>(W1, 6);

    k_zero<<<(NN + 255) / 256, 256>>>();
    k_count<<<(EE + 255) / 256, 256>>>(dst);
    k_scan<<<1, 1024>>>();
    k_bucket<<<(EE + 255) / 256, 256>>>(src, dst);

    const int GB = (NN + 127) / 128;
    const size_t smem2 = (256 * HH + 16 * HH) * sizeof(float);
    const size_t smem1 = (128 * HH + 16 * HH) * sizeof(float);
    const int AGG_BLOCKS = (NN * 32 + 255) / 256;
    const int EW_BLOCKS = (NN * HH / 4 + 255) / 256;

    // layer 0
    k_agg<<<AGG_BLOCKS, 256>>>(x);
    k_zstats<<<1, 128>>>();
    k_gemm<<<GB, 256, smem2>>>(x, bl0, 0, 256);
    k_stats<<<512, 256>>>();
    k_finstats<<<1, 128>>>();
    k_bnrelu<<<EW_BLOCKS, 256>>>();

    // layer 1
    k_agg<<<AGG_BLOCKS, 256>>>(nullptr);
    k_zstats<<<1, 128>>>();
    k_gemm<<<GB, 256, smem2>>>(nullptr, bl1, 1, 256);
    k_stats<<<512, 256>>>();
    k_finstats<<<1, 128>>>();
    k_bnrelu<<<EW_BLOCKS, 256>>>();

    // layer 2
    k_agg<<<AGG_BLOCKS, 256>>>(nullptr);
    k_zstats<<<1, 128>>>();
    k_gemm<<<GB, 256, smem2>>>(nullptr, bl2, 2, 256);
    k_stats<<<512, 256>>>();
    k_finstats<<<1, 128>>>();
    k_bnrelu<<<EW_BLOCKS, 256>>>();

    // MLP hidden layer
    k_zstats<<<1, 128>>>();
    k_gemm<<<GB, 256, smem1>>>(nullptr, b1, 3, 128);
    k_stats<<<512, 256>>>();
    k_finstats<<<1, 128>>>();
    k_bnrelu<<<EW_BLOCKS, 256>>>();

    // output projection
    k_final<<<AGG_BLOCKS, 256>>>(W2, b2, (float*)d_out);
}

// round 2
// speedup vs baseline: 1.0337x; 1.0337x over previous
#include <cuda_runtime.h>

#define NN 100000
#define EE 640000
#define HH 128
#define BN_EPS 1e-5f

// ---------------- device scratch ----------------
__device__ __align__(16) float g_agg[(size_t)NN * HH];
__device__ __align__(16) float g_y[(size_t)NN * HH];
__device__ __align__(16) float g_wt[3][2 * HH * HH];   // [layer][k'][h]: [Wl^T ; Wr^T]
__device__ __align__(16) float g_wt3[HH * HH];         // W1^T
__device__ int   g_deg[NN];
__device__ int   g_off[NN + 1];
__device__ int   g_cur[NN];
__device__ int   g_ssrc[EE];
__device__ __align__(16) float g_colsum[HH];           // zero-init; finstats re-zeroes
__device__ __align__(16) float g_colsq[HH];
__device__ __align__(16) float g_mu[HH];
__device__ __align__(16) float g_inv[HH];

// ---------------- packed f32x2 helpers ----------------
__device__ __forceinline__ void fma2(unsigned long long& d, unsigned long long a,
                                     unsigned long long b) {
    asm("fma.rn.f32x2 %0, %1, %2, %0;" : "+l"(d) : "l"(a), "l"(b));
}
__device__ __forceinline__ unsigned long long dup2(float a) {
    unsigned long long r;
    asm("mov.b64 %0, {%1, %1};" : "=l"(r) : "f"(a));
    return r;
}
__device__ __forceinline__ unsigned long long pack2(float lo, float hi) {
    unsigned long long r;
    asm("mov.b64 %0, {%1, %2};" : "=l"(r) : "f"(lo), "f"(hi));
    return r;
}
__device__ __forceinline__ void unpack2(unsigned long long v, float& lo, float& hi) {
    asm("mov.b64 {%0, %1}, %2;" : "=f"(lo), "=f"(hi) : "l"(v));
}

// ---------------- all 7 weight transposes in one launch ----------------
__global__ void k_transpose_all(const float* __restrict__ s0, const float* __restrict__ s1,
                                const float* __restrict__ s2, const float* __restrict__ s3,
                                const float* __restrict__ s4, const float* __restrict__ s5,
                                const float* __restrict__ s6) {
    const float* srcs[7] = {s0, s1, s2, s3, s4, s5, s6};
    int z = blockIdx.z;
    const float* src = srcs[z];
    float* dst = (z < 6) ? (g_wt[z >> 1] + (z & 1) * HH * HH) : g_wt3;
    __shared__ float t[32][33];
    int bx = blockIdx.x, by = blockIdx.y;
    int x = bx * 32 + threadIdx.x;
    for (int j = threadIdx.y; j < 32; j += 8)
        t[j][threadIdx.x] = src[(by * 32 + j) * HH + x];
    __syncthreads();
    int xo = by * 32 + threadIdx.x;
    for (int j = threadIdx.y; j < 32; j += 8)
        dst[(bx * 32 + j) * HH + xo] = t[threadIdx.x][j];
}

// ---------------- CSR build ----------------
__global__ void k_zero() {
    int i = blockIdx.x * blockDim.x + threadIdx.x;
    if (i < NN) { g_deg[i] = 0; g_cur[i] = 0; }
}

__global__ void k_count(const int* __restrict__ dst) {
    int e = blockIdx.x * blockDim.x + threadIdx.x;
    if (e < EE) atomicAdd(&g_deg[dst[e]], 1);
}

__global__ void k_scan() {
    __shared__ int wsum[32];
    __shared__ int carry_s;
    int tid = threadIdx.x;
    int lane = tid & 31, wid = tid >> 5;
    if (tid == 0) { carry_s = 0; g_off[0] = 0; }
    __syncthreads();
    for (int base = 0; base < NN; base += 4096) {
        int i0 = base + tid * 4;
        int a = (i0     < NN) ? g_deg[i0]     : 0;
        int b = (i0 + 1 < NN) ? g_deg[i0 + 1] : 0;
        int c = (i0 + 2 < NN) ? g_deg[i0 + 2] : 0;
        int d = (i0 + 3 < NN) ? g_deg[i0 + 3] : 0;
        int s = a + b + c + d;
        int incl = s;
#pragma unroll
        for (int o = 1; o < 32; o <<= 1) {
            int t = __shfl_up_sync(0xFFFFFFFFu, incl, o);
            if (lane >= o) incl += t;
        }
        if (lane == 31) wsum[wid] = incl;
        __syncthreads();
        if (wid == 0) {
            int v = wsum[lane];
#pragma unroll
            for (int o = 1; o < 32; o <<= 1) {
                int t = __shfl_up_sync(0xFFFFFFFFu, v, o);
                if (lane >= o) v += t;
            }
            wsum[lane] = v;
        }
        __syncthreads();
        int wpre = (wid > 0) ? wsum[wid - 1] : 0;
        int run = carry_s + wpre + incl - s;
        if (i0     < NN) g_off[i0 + 1] = run + a;
        if (i0 + 1 < NN) g_off[i0 + 2] = run + a + b;
        if (i0 + 2 < NN) g_off[i0 + 3] = run + a + b + c;
        if (i0 + 3 < NN) g_off[i0 + 4] = run + s;
        int tot = wsum[31];
        __syncthreads();
        if (tid == 0) carry_s += tot;
        __syncthreads();
    }
}

__global__ void k_bucket(const int* __restrict__ src, const int* __restrict__ dst) {
    int e = blockIdx.x * blockDim.x + threadIdx.x;
    if (e < EE) {
        int d = dst[e];
        int p = atomicAdd(&g_cur[d], 1);
        g_ssrc[g_off[d] + p] = src[e];
    }
}

// ---------------- mean aggregation (optionally fused BN+ReLU on the read) ----------------
__global__ void k_agg(const float* __restrict__ Xext, int xsel, int bn) {
    const float* X = (xsel == 0) ? Xext : g_y;
    int w = (blockIdx.x * blockDim.x + threadIdx.x) >> 5;
    int lane = threadIdx.x & 31;
    if (w >= NN) return;
    float4 m4 = make_float4(0.f, 0.f, 0.f, 0.f);
    float4 iv4 = make_float4(1.f, 1.f, 1.f, 1.f);
    if (bn) {
        m4 = *(const float4*)(g_mu + lane * 4);
        iv4 = *(const float4*)(g_inv + lane * 4);
    }
    int s = g_off[w], e = g_off[w + 1];
    float4 acc = make_float4(0.f, 0.f, 0.f, 0.f);
    float4 acc2 = make_float4(0.f, 0.f, 0.f, 0.f);
    int j = s;
    for (; j + 1 < e; j += 2) {
        int s0 = g_ssrc[j];
        int s1 = g_ssrc[j + 1];
        float4 v0 = *(const float4*)(X + (size_t)s0 * HH + lane * 4);
        float4 v1 = *(const float4*)(X + (size_t)s1 * HH + lane * 4);
        if (bn) {
            v0.x = fmaxf(0.f, (v0.x - m4.x) * iv4.x);
            v0.y = fmaxf(0.f, (v0.y - m4.y) * iv4.y);
            v0.z = fmaxf(0.f, (v0.z - m4.z) * iv4.z);
            v0.w = fmaxf(0.f, (v0.w - m4.w) * iv4.w);
            v1.x = fmaxf(0.f, (v1.x - m4.x) * iv4.x);
            v1.y = fmaxf(0.f, (v1.y - m4.y) * iv4.y);
            v1.z = fmaxf(0.f, (v1.z - m4.z) * iv4.z);
            v1.w = fmaxf(0.f, (v1.w - m4.w) * iv4.w);
        }
        acc.x += v0.x; acc.y += v0.y; acc.z += v0.z; acc.w += v0.w;
        acc2.x += v1.x; acc2.y += v1.y; acc2.z += v1.z; acc2.w += v1.w;
    }
    if (j < e) {
        int s0 = g_ssrc[j];
        float4 v0 = *(const float4*)(X + (size_t)s0 * HH + lane * 4);
        if (bn) {
            v0.x = fmaxf(0.f, (v0.x - m4.x) * iv4.x);
            v0.y = fmaxf(0.f, (v0.y - m4.y) * iv4.y);
            v0.z = fmaxf(0.f, (v0.z - m4.z) * iv4.z);
            v0.w = fmaxf(0.f, (v0.w - m4.w) * iv4.w);
        }
        acc.x += v0.x; acc.y += v0.y; acc.z += v0.z; acc.w += v0.w;
    }
    acc.x += acc2.x; acc.y += acc2.y; acc.z += acc2.z; acc.w += acc2.w;
    int d = e - s;
    float invd = (d > 0) ? (1.0f / (float)d) : 0.0f;
    acc.x *= invd; acc.y *= invd; acc.z *= invd; acc.w *= invd;
    *(float4*)(g_agg + (size_t)w * HH + lane * 4) = acc;
}

// ---------------- A-tile loader with optional fused BN+ReLU ----------------
__device__ __forceinline__ float4 ld_bn(const float* __restrict__ S, int row, int kk, int bn) {
    float4 v = *(const float4*)(S + (size_t)row * HH + kk);
    if (bn) {
        float4 m = *(const float4*)(g_mu + kk);
        float4 iv = *(const float4*)(g_inv + kk);
        v.x = fmaxf(0.f, (v.x - m.x) * iv.x);
        v.y = fmaxf(0.f, (v.y - m.y) * iv.y);
        v.z = fmaxf(0.f, (v.z - m.z) * iv.z);
        v.w = fmaxf(0.f, (v.w - m.w) * iv.w);
    }
    return v;
}

// ---------------- fused SGEMM (f32x2) + bias + column stats epilogue ----------------
// block tile 128x128, 256 threads, thread tile 8x8 (as 8x4 f32x2 pairs)
__global__ void __launch_bounds__(256) k_gemm(const float* __restrict__ Aext,
                                              const float* __restrict__ bias,
                                              int wsel, int Ktot,
                                              int asel, int bsel, int bnA, int bnB) {
    const float* PA = (asel == 1) ? g_agg : ((asel == 2) ? g_y : Aext);
    const float* PB = (bsel == 1) ? g_agg : ((bsel == 2) ? g_y : Aext);
    const float* WT = (wsel < 3) ? g_wt[wsel] : g_wt3;
    extern __shared__ float sm[];
    float* Bs = sm;                 // [Ktot][128]
    float* As = sm + Ktot * HH;     // 2 x [8][128]  (reused as [16][128] staging)

    int tid = threadIdx.x;
    int tx = tid & 15, ty = tid >> 4;
    int m0 = blockIdx.x * 128;

    for (int idx = tid * 4; idx < Ktot * HH; idx += 1024)
        *(float4*)(Bs + idx) = *(const float4*)(WT + idx);

    int lrow = tid & 127;
    int kq = (tid >> 7) * 4;          // 0 or 4
    int grow = m0 + lrow;
    bool rok = grow < NN;

    unsigned long long acc[8][4];
#pragma unroll
    for (int i = 0; i < 8; i++)
#pragma unroll
        for (int j = 0; j < 4; j++) acc[i][j] = 0ull;

    int nk = Ktot / 8;

    // chunk 0 (gk = kq < 128 -> PA)
    {
        float4 av = rok ? ld_bn(PA, grow, kq, bnA) : make_float4(0.f, 0.f, 0.f, 0.f);
        As[(kq + 0) * HH + lrow] = av.x;
        As[(kq + 1) * HH + lrow] = av.y;
        As[(kq + 2) * HH + lrow] = av.z;
        As[(kq + 3) * HH + lrow] = av.w;
    }
    __syncthreads();

    for (int kc = 0; kc < nk; kc++) {
        float4 nxt = make_float4(0.f, 0.f, 0.f, 0.f);
        if (kc + 1 < nk) {
            int gk = (kc + 1) * 8 + kq;
            if (rok) {
                if (gk >= 128) nxt = ld_bn(PB, grow, gk - 128, bnB);
                else           nxt = ld_bn(PA, grow, gk, bnA);
            }
        }
        const float* cur = As + (kc & 1) * 8 * HH;
#pragma unroll
        for (int kk = 0; kk < 8; kk++) {
            float4 a0 = *(const float4*)(cur + kk * HH + ty * 4);
            float4 a1 = *(const float4*)(cur + kk * HH + ty * 4 + 64);
            const float* br = Bs + (kc * 8 + kk) * HH;
            float4 b0 = *(const float4*)(br + tx * 4);
            float4 b1 = *(const float4*)(br + tx * 4 + 64);
            unsigned long long ap[8];
            ap[0] = dup2(a0.x); ap[1] = dup2(a0.y); ap[2] = dup2(a0.z); ap[3] = dup2(a0.w);
            ap[4] = dup2(a1.x); ap[5] = dup2(a1.y); ap[6] = dup2(a1.z); ap[7] = dup2(a1.w);
            unsigned long long bp[4];
            bp[0] = pack2(b0.x, b0.y); bp[1] = pack2(b0.z, b0.w);
            bp[2] = pack2(b1.x, b1.y); bp[3] = pack2(b1.z, b1.w);
#pragma unroll
            for (int i = 0; i < 8; i++)
#pragma unroll
                for (int j = 0; j < 4; j++)
                    fma2(acc[i][j], ap[i], bp[j]);
        }
        if (kc + 1 < nk) {
            float* D = As + ((kc + 1) & 1) * 8 * HH;
            D[(kq + 0) * HH + lrow] = nxt.x;
            D[(kq + 1) * HH + lrow] = nxt.y;
            D[(kq + 2) * HH + lrow] = nxt.z;
            D[(kq + 3) * HH + lrow] = nxt.w;
        }
        __syncthreads();
    }

    // epilogue: bias add, store, per-column partial stats
    float4 bi0 = *(const float4*)(bias + tx * 4);
    float4 bi1 = *(const float4*)(bias + tx * 4 + 64);
    float bi[8] = {bi0.x, bi0.y, bi0.z, bi0.w, bi1.x, bi1.y, bi1.z, bi1.w};
    float s[8], q[8];
#pragma unroll
    for (int j = 0; j < 8; j++) { s[j] = 0.f; q[j] = 0.f; }

#pragma unroll
    for (int i = 0; i < 8; i++) {
        int row = m0 + ty * 4 + ((i < 4) ? i : (60 + i));
        float o[8];
        unpack2(acc[i][0], o[0], o[1]);
        unpack2(acc[i][1], o[2], o[3]);
        unpack2(acc[i][2], o[4], o[5]);
        unpack2(acc[i][3], o[6], o[7]);
        if (row < NN) {
#pragma unroll
            for (int j = 0; j < 8; j++) {
                o[j] += bi[j];
                s[j] += o[j];
                q[j] += o[j] * o[j];
            }
            float4 o0 = make_float4(o[0], o[1], o[2], o[3]);
            float4 o1 = make_float4(o[4], o[5], o[6], o[7]);
            *(float4*)(g_y + (size_t)row * HH + tx * 4) = o0;
            *(float4*)(g_y + (size_t)row * HH + tx * 4 + 64) = o1;
        }
    }

    // staged column reduction through shared (reuse As region: 16x128 floats)
    float* stg = As;
#pragma unroll
    for (int j = 0; j < 4; j++) {
        stg[ty * 128 + tx * 4 + j] = s[j];
        stg[ty * 128 + tx * 4 + 64 + j] = s[j + 4];
    }
    __syncthreads();
    if (tid < 128) {
        float t = 0.f;
#pragma unroll
        for (int r = 0; r < 16; r++) t += stg[r * 128 + tid];
        atomicAdd(&g_colsum[tid], t);
    }
    __syncthreads();
#pragma unroll
    for (int j = 0; j < 4; j++) {
        stg[ty * 128 + tx * 4 + j] = q[j];
        stg[ty * 128 + tx * 4 + 64 + j] = q[j + 4];
    }
    __syncthreads();
    if (tid < 128) {
        float t = 0.f;
#pragma unroll
        for (int r = 0; r < 16; r++) t += stg[r * 128 + tid];
        atomicAdd(&g_colsq[tid], t);
    }
}

// ---------------- finalize stats (and re-zero accumulators) ----------------
__global__ void k_finstats() {
    int c = threadIdx.x;
    float mu = g_colsum[c] / (float)NN;
    float var = g_colsq[c] / (float)NN - mu * mu;
    g_mu[c] = mu;
    g_inv[c] = rsqrtf(var + BN_EPS);
    g_colsum[c] = 0.f;
    g_colsq[c] = 0.f;
}

// ---------------- final projection (fused BN+ReLU on read) ----------------
__global__ void k_final(const float* __restrict__ W2, const float* __restrict__ b2,
                        float* __restrict__ out) {
    int w = (blockIdx.x * blockDim.x + threadIdx.x) >> 5;
    int lane = threadIdx.x & 31;
    if (w >= NN) return;
    float4 m4 = *(const float4*)(g_mu + lane * 4);
    float4 iv4 = *(const float4*)(g_inv + lane * 4);
    float4 xv = *(const float4*)(g_y + (size_t)w * HH + lane * 4);
    xv.x = fmaxf(0.f, (xv.x - m4.x) * iv4.x);
    xv.y = fmaxf(0.f, (xv.y - m4.y) * iv4.y);
    xv.z = fmaxf(0.f, (xv.z - m4.z) * iv4.z);
    xv.w = fmaxf(0.f, (xv.w - m4.w) * iv4.w);
    float4 w0 = *(const float4*)(W2 + lane * 4);
    float4 w1 = *(const float4*)(W2 + HH + lane * 4);
    float d0 = xv.x * w0.x + xv.y * w0.y + xv.z * w0.z + xv.w * w0.w;
    float d1 = xv.x * w1.x + xv.y * w1.y + xv.z * w1.z + xv.w * w1.w;
#pragma unroll
    for (int o = 16; o; o >>= 1) {
        d0 += __shfl_xor_sync(0xFFFFFFFFu, d0, o);
        d1 += __shfl_xor_sync(0xFFFFFFFFu, d1, o);
    }
    if (lane == 0) {
        out[(size_t)w * 2 + 0] = d0 + b2[0];
        out[(size_t)w * 2 + 1] = d1 + b2[1];
    }
}

// ---------------- host launch ----------------
extern "C" void kernel_launch(void* const* d_in, const int* in_sizes, int n_in,
                              void* d_out, int out_size) {
    const float* x   = (const float*)d_in[0];
    const int*   ei  = (const int*)d_in[1];
    const int*   src = ei;
    const int*   dst = ei + EE;
    const float* Wl0 = (const float*)d_in[2];
    const float* bl0 = (const float*)d_in[3];
    const float* Wr0 = (const float*)d_in[4];
    const float* Wl1 = (const float*)d_in[5];
    const float* bl1 = (const float*)d_in[6];
    const float* Wr1 = (const float*)d_in[7];
    const float* Wl2 = (const float*)d_in[8];
    const float* bl2 = (const float*)d_in[9];
    const float* Wr2 = (const float*)d_in[10];
    const float* W1  = (const float*)d_in[11];
    const float* b1  = (const float*)d_in[12];
    const float* W2  = (const float*)d_in[13];
    const float* b2  = (const float*)d_in[14];

    static int smem_set = 0;
    if (!smem_set) {
        cudaFuncSetAttribute(k_gemm, cudaFuncAttributeMaxDynamicSharedMemorySize, 139264);
        smem_set = 1;
    }

    k_transpose_all<<<dim3(4, 4, 7), dim3(32, 8)>>>(Wl0, Wr0, Wl1, Wr1, Wl2, Wr2, W1);

    k_zero<<<(NN + 255) / 256, 256>>>();
    k_count<<<(EE + 255) / 256, 256>>>(dst);
    k_scan<<<1, 1024>>>();
    k_bucket<<<(EE + 255) / 256, 256>>>(src, dst);

    const int GB = (NN + 127) / 128;
    const size_t smem2 = (256 * HH + 16 * HH) * sizeof(float);
    const size_t smem1 = (128 * HH + 16 * HH) * sizeof(float);
    const int AGG_BLOCKS = (NN * 32 + 255) / 256;

    // layer 0: inputs raw x
    k_agg<<<AGG_BLOCKS, 256>>>(x, 0, 0);
    k_gemm<<<GB, 256, smem2>>>(x, bl0, 0, 256, /*asel=*/1, /*bsel=*/0, /*bnA=*/0, /*bnB=*/0);
    k_finstats<<<1, 128>>>();

    // layer 1: inputs relu(bn(y0)) read on the fly from g_y
    k_agg<<<AGG_BLOCKS, 256>>>(nullptr, 1, 1);
    k_gemm<<<GB, 256, smem2>>>(nullptr, bl1, 1, 256, 1, 2, 0, 1);
    k_finstats<<<1, 128>>>();

    // layer 2
    k_agg<<<AGG_BLOCKS, 256>>>(nullptr, 1, 1);
    k_gemm<<<GB, 256, smem2>>>(nullptr, bl2, 2, 256, 1, 2, 0, 1);
    k_finstats<<<1, 128>>>();

    // MLP hidden layer: reads relu(bn(y2)) from g_y, K=128
    k_gemm<<<GB, 256, smem1>>>(nullptr, b1, 3, 128, 2, 2, 1, 0);
    k_finstats<<<1, 128>>>();

    // output projection: reads relu(bn(y3))
    k_final<<<AGG_BLOCKS, 256>>>(W2, b2, (float*)d_out);
}

// round 3
// speedup vs baseline: 1.4913x; 1.4426x over previous
#include <cuda_runtime.h>
#include <cstdint>

#define NN 100000
#define EE 640000
#define HH 128
#define BN_EPS 1e-5f
#define NB 391            // ceil(NN/256)
#define GB 782            // ceil(NN/128)

// ---------------- device scratch ----------------
__device__ __align__(16) float g_agg[(size_t)NN * HH];
__device__ __align__(16) float g_y[(size_t)NN * HH];
__device__ int   g_deg[NN];
__device__ int   g_off[NN + 1];
__device__ int   g_cur[NN];
__device__ int   g_ssrc[EE];
__device__ int   g_bpart[512];
__device__ int   g_bbase[512];
__device__ __align__(16) float g_colsum[HH];   // zero-init; finstats re-zeroes
__device__ __align__(16) float g_colsq[HH];
__device__ __align__(16) float g_mu[HH];
__device__ __align__(16) float g_inv[HH];

// ---------------- tf32 helpers ----------------
__device__ __forceinline__ uint32_t f2tf(float x) {
    uint32_t r;
    asm("cvt.rna.tf32.f32 %0, %1;" : "=r"(r) : "f"(x));
    return r;
}
__device__ __forceinline__ void tfsplit(float v, uint32_t& hi, uint32_t& lo) {
    hi = f2tf(v);
    lo = f2tf(v - __uint_as_float(hi));
}
__device__ __forceinline__ void mma8(float* c, const uint32_t* a, uint32_t b0, uint32_t b1) {
    asm("mma.sync.aligned.m16n8k8.row.col.f32.tf32.tf32.f32 "
        "{%0,%1,%2,%3},{%4,%5,%6,%7},{%8,%9},{%0,%1,%2,%3};"
        : "+f"(c[0]), "+f"(c[1]), "+f"(c[2]), "+f"(c[3])
        : "r"(a[0]), "r"(a[1]), "r"(a[2]), "r"(a[3]), "r"(b0), "r"(b1));
}

// ---------------- CSR build ----------------
__global__ void k_zero() {
    int i = blockIdx.x * blockDim.x + threadIdx.x;
    if (i < NN) { g_deg[i] = 0; g_cur[i] = 0; }
}

__global__ void k_count(const int* __restrict__ dst) {
    int e = blockIdx.x * blockDim.x + threadIdx.x;
    if (e < EE) atomicAdd(&g_deg[dst[e]], 1);
}

// block partial sums of degrees
__global__ void k_part() {
    __shared__ int ws[8];
    int i = blockIdx.x * 256 + threadIdx.x;
    int v = (i < NN) ? g_deg[i] : 0;
    int lane = threadIdx.x & 31, wid = threadIdx.x >> 5;
    int s = v;
#pragma unroll
    for (int o = 16; o; o >>= 1) s += __shfl_xor_sync(0xFFFFFFFFu, s, o);
    if (lane == 0) ws[wid] = s;
    __syncthreads();
    if (threadIdx.x == 0) {
        int t = 0;
#pragma unroll
        for (int w = 0; w < 8; w++) t += ws[w];
        g_bpart[blockIdx.x] = t;
    }
}

// scan the 391 block partials (one block of 512)
__global__ void k_scanp() {
    __shared__ int ws[16];
    int t = threadIdx.x;
    int lane = t & 31, wid = t >> 5;
    int v = (t < NB) ? g_bpart[t] : 0;
    int incl = v;
#pragma unroll
    for (int o = 1; o < 32; o <<= 1) {
        int u = __shfl_up_sync(0xFFFFFFFFu, incl, o);
        if (lane >= o) incl += u;
    }
    if (lane == 31) ws[wid] = incl;
    __syncthreads();
    if (wid == 0 && lane < 16) {
        int u = ws[lane];
#pragma unroll
        for (int o = 1; o < 16; o <<= 1) {
            int p = __shfl_up_sync(0xFFFFu, u, o);
            if (lane >= o) u += p;
        }
        ws[lane] = u;
    }
    __syncthreads();
    int wpre = (wid > 0) ? ws[wid - 1] : 0;
    if (t < NB) g_bbase[t] = wpre + incl - v;   // exclusive base per block
    if (t == 0) g_off[0] = 0;
}

// per-block inclusive scan + base -> offsets
__global__ void k_apply() {
    __shared__ int ws[8];
    int i = blockIdx.x * 256 + threadIdx.x;
    int lane = threadIdx.x & 31, wid = threadIdx.x >> 5;
    int v = (i < NN) ? g_deg[i] : 0;
    int incl = v;
#pragma unroll
    for (int o = 1; o < 32; o <<= 1) {
        int u = __shfl_up_sync(0xFFFFFFFFu, incl, o);
        if (lane >= o) incl += u;
    }
    if (lane == 31) ws[wid] = incl;
    __syncthreads();
    if (wid == 0 && lane < 8) {
        int u = ws[lane];
#pragma unroll
        for (int o = 1; o < 8; o <<= 1) {
            int p = __shfl_up_sync(0xFFu, u, o);
            if (lane >= o) u += p;
        }
        ws[lane] = u;
    }
    __syncthreads();
    int wpre = (wid > 0) ? ws[wid - 1] : 0;
    if (i < NN) g_off[i + 1] = g_bbase[blockIdx.x] + wpre + incl;
}

__global__ void k_bucket(const int* __restrict__ src, const int* __restrict__ dst) {
    int e = blockIdx.x * blockDim.x + threadIdx.x;
    if (e < EE) {
        int d = dst[e];
        int p = atomicAdd(&g_cur[d], 1);
        g_ssrc[g_off[d] + p] = src[e];
    }
}

// ---------------- mean aggregation (optionally fused BN+ReLU on the read) ----------------
__global__ void k_agg(const float* __restrict__ Xext, int xsel, int bn) {
    const float* X = (xsel == 0) ? Xext : g_y;
    int w = (blockIdx.x * blockDim.x + threadIdx.x) >> 5;
    int lane = threadIdx.x & 31;
    if (w >= NN) return;
    float4 m4 = make_float4(0.f, 0.f, 0.f, 0.f);
    float4 iv4 = make_float4(1.f, 1.f, 1.f, 1.f);
    if (bn) {
        m4 = *(const float4*)(g_mu + lane * 4);
        iv4 = *(const float4*)(g_inv + lane * 4);
    }
    int s = g_off[w], e = g_off[w + 1];
    float4 acc = make_float4(0.f, 0.f, 0.f, 0.f);
    float4 acc2 = make_float4(0.f, 0.f, 0.f, 0.f);
    int j = s;
    for (; j + 1 < e; j += 2) {
        int s0 = g_ssrc[j];
        int s1 = g_ssrc[j + 1];
        float4 v0 = *(const float4*)(X + (size_t)s0 * HH + lane * 4);
        float4 v1 = *(const float4*)(X + (size_t)s1 * HH + lane * 4);
        if (bn) {
            v0.x = fmaxf(0.f, (v0.x - m4.x) * iv4.x);
            v0.y = fmaxf(0.f, (v0.y - m4.y) * iv4.y);
            v0.z = fmaxf(0.f, (v0.z - m4.z) * iv4.z);
            v0.w = fmaxf(0.f, (v0.w - m4.w) * iv4.w);
            v1.x = fmaxf(0.f, (v1.x - m4.x) * iv4.x);
            v1.y = fmaxf(0.f, (v1.y - m4.y) * iv4.y);
            v1.z = fmaxf(0.f, (v1.z - m4.z) * iv4.z);
            v1.w = fmaxf(0.f, (v1.w - m4.w) * iv4.w);
        }
        acc.x += v0.x; acc.y += v0.y; acc.z += v0.z; acc.w += v0.w;
        acc2.x += v1.x; acc2.y += v1.y; acc2.z += v1.z; acc2.w += v1.w;
    }
    if (j < e) {
        int s0 = g_ssrc[j];
        float4 v0 = *(const float4*)(X + (size_t)s0 * HH + lane * 4);
        if (bn) {
            v0.x = fmaxf(0.f, (v0.x - m4.x) * iv4.x);
            v0.y = fmaxf(0.f, (v0.y - m4.y) * iv4.y);
            v0.z = fmaxf(0.f, (v0.z - m4.z) * iv4.z);
            v0.w = fmaxf(0.f, (v0.w - m4.w) * iv4.w);
        }
        acc.x += v0.x; acc.y += v0.y; acc.z += v0.z; acc.w += v0.w;
    }
    acc.x += acc2.x; acc.y += acc2.y; acc.z += acc2.z; acc.w += acc2.w;
    int d = e - s;
    float invd = (d > 0) ? (1.0f / (float)d) : 0.0f;
    acc.x *= invd; acc.y *= invd; acc.z *= invd; acc.w *= invd;
    *(float4*)(g_agg + (size_t)w * HH + lane * 4) = acc;
}

// ---------------- BN+ReLU fused load ----------------
__device__ __forceinline__ float4 ld_bn(const float* __restrict__ S, int row, int kk, int bn) {
    float4 v = *(const float4*)(S + (size_t)row * HH + kk);
    if (bn) {
        float4 m = *(const float4*)(g_mu + kk);
        float4 iv = *(const float4*)(g_inv + kk);
        v.x = fmaxf(0.f, (v.x - m.x) * iv.x);
        v.y = fmaxf(0.f, (v.y - m.y) * iv.y);
        v.z = fmaxf(0.f, (v.z - m.z) * iv.z);
        v.w = fmaxf(0.f, (v.w - m.w) * iv.w);
    }
    return v;
}

// ---------------- tensor-core SGEMM (3xTF32) + bias + column stats ----------------
// block 128x128, 8 warps (warp tile 32x64), K step 8, double-buffered smem stride 12
__global__ void __launch_bounds__(256, 2) k_gemm(const float* __restrict__ Aext,
                                                 const float* __restrict__ Wl,
                                                 const float* __restrict__ Wr,
                                                 const float* __restrict__ bias,
                                                 int Ktot, int asel, int bsel,
                                                 int bnA, int bnB) {
    const float* PA = (asel == 1) ? g_agg : ((asel == 2) ? g_y : Aext);
    const float* PB = (bsel == 1) ? g_agg : ((bsel == 2) ? g_y : Aext);
    __shared__ float smA[2][128 * 12];
    __shared__ float smB[2][128 * 12];

    int tid = threadIdx.x;
    int lane = tid & 31, warp = tid >> 5;
    int wm = warp >> 1, wn = warp & 1;
    int m0 = blockIdx.x * 128;
    int nk = Ktot / 8;

    float acc[2][8][4];
#pragma unroll
    for (int mt = 0; mt < 2; mt++)
#pragma unroll
        for (int nt = 0; nt < 8; nt++)
#pragma unroll
            for (int j = 0; j < 4; j++) acc[mt][nt][j] = 0.f;

    const int lrow = tid >> 1;          // 0..127
    const int lk = (tid & 1) * 4;       // 0 or 4
    const int grow = m0 + lrow;
    const bool rok = grow < NN;

    // step-0 load
    float4 a4, b4;
    {
        int gk = lk;
        a4 = rok ? ((Ktot == 256 || 1) ? ld_bn(PA, grow, gk, bnA) : make_float4(0, 0, 0, 0))
                 : make_float4(0.f, 0.f, 0.f, 0.f);
        b4 = *(const float4*)(Wl + lrow * 128 + gk);
    }
    *(float4*)(&smA[0][lrow * 12 + lk]) = a4;
    *(float4*)(&smB[0][lrow * 12 + lk]) = b4;
    __syncthreads();

    for (int kc = 0; kc < nk; kc++) {
        // prefetch next chunk to regs
        if (kc + 1 < nk) {
            int gk = (kc + 1) * 8 + lk;
            if (rok) {
                if (gk >= 128) a4 = ld_bn(PB, grow, gk - 128, bnB);
                else           a4 = ld_bn(PA, grow, gk, bnA);
            } else {
                a4 = make_float4(0.f, 0.f, 0.f, 0.f);
            }
            const float* W = (gk < 128) ? Wl : Wr;
            b4 = *(const float4*)(W + lrow * 128 + (gk & 127));
        }

        const float* A = smA[kc & 1];
        const float* B = smB[kc & 1];

        uint32_t ah[8], al[8];
#pragma unroll
        for (int mt = 0; mt < 2; mt++)
#pragma unroll
            for (int j = 0; j < 4; j++) {
                int row = wm * 32 + mt * 16 + (lane >> 2) + (j & 1) * 8;
                int kk = (lane & 3) + (j >> 1) * 4;
                tfsplit(A[row * 12 + kk], ah[mt * 4 + j], al[mt * 4 + j]);
            }
#pragma unroll
        for (int nt = 0; nt < 8; nt++) {
            int n = wn * 64 + nt * 8 + (lane >> 2);
            int kk = lane & 3;
            uint32_t bh0, bl0, bh1, bl1;
            tfsplit(B[n * 12 + kk], bh0, bl0);
            tfsplit(B[n * 12 + kk + 4], bh1, bl1);
#pragma unroll
            for (int mt = 0; mt < 2; mt++) {
                mma8(acc[mt][nt], ah + mt * 4, bh0, bh1);
                mma8(acc[mt][nt], ah + mt * 4, bl0, bl1);
                mma8(acc[mt][nt], al + mt * 4, bh0, bh1);
            }
        }

        if (kc + 1 < nk) {
            float* DA = smA[(kc + 1) & 1];
            float* DB = smB[(kc + 1) & 1];
            *(float4*)(&DA[lrow * 12 + lk]) = a4;
            *(float4*)(&DB[lrow * 12 + lk]) = b4;
        }
        __syncthreads();
    }

    // ---------------- epilogue: bias, store, column stats ----------------
    float bc[16];
#pragma unroll
    for (int nt = 0; nt < 8; nt++) {
        int c0 = wn * 64 + nt * 8 + 2 * (lane & 3);
        bc[nt * 2 + 0] = bias[c0];
        bc[nt * 2 + 1] = bias[c0 + 1];
    }

    float s[16], q[16];
#pragma unroll
    for (int j = 0; j < 16; j++) { s[j] = 0.f; q[j] = 0.f; }

#pragma unroll
    for (int mt = 0; mt < 2; mt++) {
        int r0 = m0 + wm * 32 + mt * 16 + (lane >> 2);
        int r1 = r0 + 8;
        bool ok0 = r0 < NN, ok1 = r1 < NN;
#pragma unroll
        for (int nt = 0; nt < 8; nt++) {
            int c0 = wn * 64 + nt * 8 + 2 * (lane & 3);
            float o0 = acc[mt][nt][0] + bc[nt * 2 + 0];
            float o1 = acc[mt][nt][1] + bc[nt * 2 + 1];
            float o2 = acc[mt][nt][2] + bc[nt * 2 + 0];
            float o3 = acc[mt][nt][3] + bc[nt * 2 + 1];
            if (ok0) {
                *(float2*)(g_y + (size_t)r0 * HH + c0) = make_float2(o0, o1);
                s[nt * 2 + 0] += o0; q[nt * 2 + 0] += o0 * o0;
                s[nt * 2 + 1] += o1; q[nt * 2 + 1] += o1 * o1;
            }
            if (ok1) {
                *(float2*)(g_y + (size_t)r1 * HH + c0) = make_float2(o2, o3);
                s[nt * 2 + 0] += o2; q[nt * 2 + 0] += o2 * o2;
                s[nt * 2 + 1] += o3; q[nt * 2 + 1] += o3 * o3;
            }
        }
    }

    // reduce over the 8 row-groups within the warp (lanes differing in bits 2..4)
#pragma unroll
    for (int j = 0; j < 16; j++) {
#pragma unroll
        for (int o = 4; o <= 16; o <<= 1) {
            s[j] += __shfl_xor_sync(0xFFFFFFFFu, s[j], o);
            q[j] += __shfl_xor_sync(0xFFFFFFFFu, q[j], o);
        }
    }

    float* stage = smA[0];   // reuse: [8 warps][128 cols]
    if (lane < 4) {
#pragma unroll
        for (int nt = 0; nt < 8; nt++) {
            int c = wn * 64 + nt * 8 + 2 * lane;
            stage[warp * 128 + c] = s[nt * 2 + 0];
            stage[warp * 128 + c + 1] = s[nt * 2 + 1];
        }
    }
    __syncthreads();
    if (tid < 128) {
        int cn = tid >> 6;   // which warp_n covers this column
        float t = stage[(0 * 2 + cn) * 128 + tid] + stage[(1 * 2 + cn) * 128 + tid] +
                  stage[(2 * 2 + cn) * 128 + tid] + stage[(3 * 2 + cn) * 128 + tid];
        atomicAdd(&g_colsum[tid], t);
    }
    __syncthreads();
    if (lane < 4) {
#pragma unroll
        for (int nt = 0; nt < 8; nt++) {
            int c = wn * 64 + nt * 8 + 2 * lane;
            stage[warp * 128 + c] = q[nt * 2 + 0];
            stage[warp * 128 + c + 1] = q[nt * 2 + 1];
        }
    }
    __syncthreads();
    if (tid < 128) {
        int cn = tid >> 6;
        float t = stage[(0 * 2 + cn) * 128 + tid] + stage[(1 * 2 + cn) * 128 + tid] +
                  stage[(2 * 2 + cn) * 128 + tid] + stage[(3 * 2 + cn) * 128 + tid];
        atomicAdd(&g_colsq[tid], t);
    }
}

// ---------------- finalize stats (and re-zero accumulators) ----------------
__global__ void k_finstats() {
    int c = threadIdx.x;
    float mu = g_colsum[c] / (float)NN;
    float var = g_colsq[c] / (float)NN - mu * mu;
    g_mu[c] = mu;
    g_inv[c] = rsqrtf(var + BN_EPS);
    g_colsum[c] = 0.f;
    g_colsq[c] = 0.f;
}

// ---------------- final projection (fused BN+ReLU on read) ----------------
__global__ void k_final(const float* __restrict__ W2, const float* __restrict__ b2,
                        float* __restrict__ out) {
    int w = (blockIdx.x * blockDim.x + threadIdx.x) >> 5;
    int lane = threadIdx.x & 31;
    if (w >= NN) return;
    float4 m4 = *(const float4*)(g_mu + lane * 4);
    float4 iv4 = *(const float4*)(g_inv + lane * 4);
    float4 xv = *(const float4*)(g_y + (size_t)w * HH + lane * 4);
    xv.x = fmaxf(0.f, (xv.x - m4.x) * iv4.x);
    xv.y = fmaxf(0.f, (xv.y - m4.y) * iv4.y);
    xv.z = fmaxf(0.f, (xv.z - m4.z) * iv4.z);
    xv.w = fmaxf(0.f, (xv.w - m4.w) * iv4.w);
    float4 w0 = *(const float4*)(W2 + lane * 4);
    float4 w1 = *(const float4*)(W2 + HH + lane * 4);
    float d0 = xv.x * w0.x + xv.y * w0.y + xv.z * w0.z + xv.w * w0.w;
    float d1 = xv.x * w1.x + xv.y * w1.y + xv.z * w1.z + xv.w * w1.w;
#pragma unroll
    for (int o = 16; o; o >>= 1) {
        d0 += __shfl_xor_sync(0xFFFFFFFFu, d0, o);
        d1 += __shfl_xor_sync(0xFFFFFFFFu, d1, o);
    }
    if (lane == 0) {
        out[(size_t)w * 2 + 0] = d0 + b2[0];
        out[(size_t)w * 2 + 1] = d1 + b2[1];
    }
}

// ---------------- host launch ----------------
extern "C" void kernel_launch(void* const* d_in, const int* in_sizes, int n_in,
                              void* d_out, int out_size) {
    const float* x   = (const float*)d_in[0];
    const int*   ei  = (const int*)d_in[1];
    const int*   src = ei;
    const int*   dst = ei + EE;
    const float* Wl0 = (const float*)d_in[2];
    const float* bl0 = (const float*)d_in[3];
    const float* Wr0 = (const float*)d_in[4];
    const float* Wl1 = (const float*)d_in[5];
    const float* bl1 = (const float*)d_in[6];
    const float* Wr1 = (const float*)d_in[7];
    const float* Wl2 = (const float*)d_in[8];
    const float* bl2 = (const float*)d_in[9];
    const float* Wr2 = (const float*)d_in[10];
    const float* W1  = (const float*)d_in[11];
    const float* b1  = (const float*)d_in[12];
    const float* W2  = (const float*)d_in[13];
    const float* b2  = (const float*)d_in[14];

    // CSR build
    k_zero<<<NB, 256>>>();
    k_count<<<(EE + 255) / 256, 256>>>(dst);
    k_part<<<NB, 256>>>();
    k_scanp<<<1, 512>>>();
    k_apply<<<NB, 256>>>();
    k_bucket<<<(EE + 255) / 256, 256>>>(src, dst);

    const int AGG_BLOCKS = (NN * 32 + 255) / 256;

    // layer 0: inputs raw x
    k_agg<<<AGG_BLOCKS, 256>>>(x, 0, 0);
    k_gemm<<<GB, 256>>>(x, Wl0, Wr0, bl0, 256, /*asel=*/1, /*bsel=*/0, 0, 0);
    k_finstats<<<1, 128>>>();

    // layer 1: agg over relu(bn(y0)); dense part reads g_y with fused bn
    k_agg<<<AGG_BLOCKS, 256>>>(nullptr, 1, 1);
    k_gemm<<<GB, 256>>>(nullptr, Wl1, Wr1, bl1, 256, 1, 2, 0, 1);
    k_finstats<<<1, 128>>>();

    // layer 2
    k_agg<<<AGG_BLOCKS, 256>>>(nullptr, 1, 1);
    k_gemm<<<GB, 256>>>(nullptr, Wl2, Wr2, bl2, 256, 1, 2, 0, 1);
    k_finstats<<<1, 128>>>();

    // MLP hidden: y = relu(bn(y2)) @ W1^T + b1, K=128
    k_gemm<<<GB, 256>>>(nullptr, W1, W1, b1, 128, 2, 2, 1, 1);
    k_finstats<<<1, 128>>>();

    // output projection
    k_final<<<AGG_BLOCKS, 256>>>(W2, b2, (float*)d_out);
}